// round 9
// baseline (speedup 1.0000x reference)
#include <cuda_runtime.h>
#include <math.h>

#define NB  8
#define CC  64
#define HH  512
#define WW  257
#define BB  8
#define NN  (HH*WW)        // 131584
#define NG  (NN/4)         // 32896 float4 groups per batch
#define NG8 (NN/8)         // 16448 8-pixel units per batch
#define GX8 ((NG8 + 255) / 256)   // 65 blocks in x
#define TOTAL_BLOCKS (GX8 * BB)   // 520

// Device-global scratch (no cudaMalloc allowed). Zero at module load; the
// fused MLP phase snapshots then resets everything, so each graph replay
// starts from a clean state. g_bands4 is rewritten identically every call.
__device__ float        g_acc[BB][NB][4];  // shifted moments
__device__ float        g_cnt[NB];
__device__ float        g_alpha[BB*NB];
__device__ unsigned int g_ticket;
__device__ uchar4       g_bands4[NG];      // band ids per float4 group

#define XSHIFT 0.8f   // x = mean-over-channels log1p(|z|) is ~0.81 +- 0.05

__device__ __forceinline__ float f_sqrt_approx(float x){
    float r; asm("sqrt.approx.f32 %0, %1;" : "=f"(r) : "f"(x)); return r;
}
__device__ __forceinline__ float f_lg2_approx(float x){
    float r; asm("lg2.approx.f32 %0, %1;" : "=f"(r) : "f"(x)); return r;
}

// Exact replication of the reference band assignment (bit-identical fp32 ops).
__device__ __forceinline__ int band_of(int n){
    int iy = n / WW;
    int ix = n - iy * WW;
    float fy = (float)(iy < 256 ? iy : iy - 512) * (1.0f/512.0f);
    float fx = (float)ix * (1.0f/512.0f);
    float r  = __fsqrt_rn(fx*fx + fy*fy);
    float rn = __fdiv_rn(r, 0.70710678118654752440f);
    int band = (rn > 0.125f) + (rn > 0.25f) + (rn > 0.375f) + (rn > 0.5f)
             + (rn > 0.625f) + (rn > 0.75f) + (rn > 0.875f);
    return band;
}

__device__ __forceinline__ float fixf(float x){
    if (isnan(x)) return 0.0f;
    if (isinf(x)) return x > 0.f ? 50.0f : -50.0f;
    return x;
}

// multiply 8 products by (1 + |z|) from two float4 pairs
#define MAG8(P, R0, I0, R1, I1)                                        \
    P[0] *= 1.0f + f_sqrt_approx((R0).x*(R0).x + (I0).x*(I0).x);       \
    P[1] *= 1.0f + f_sqrt_approx((R0).y*(R0).y + (I0).y*(I0).y);       \
    P[2] *= 1.0f + f_sqrt_approx((R0).z*(R0).z + (I0).z*(I0).z);       \
    P[3] *= 1.0f + f_sqrt_approx((R0).w*(R0).w + (I0).w*(I0).w);       \
    P[4] *= 1.0f + f_sqrt_approx((R1).x*(R1).x + (I1).x*(I1).x);       \
    P[5] *= 1.0f + f_sqrt_approx((R1).y*(R1).y + (I1).y*(I1).y);       \
    P[6] *= 1.0f + f_sqrt_approx((R1).z*(R1).z + (I1).z*(I1).z);       \
    P[7] *= 1.0f + f_sqrt_approx((R1).w*(R1).w + (I1).w*(I1).w);

__global__ void __launch_bounds__(256)
k_reduce(const float* __restrict__ lre, const float* __restrict__ lim,
         const float* __restrict__ hre, const float* __restrict__ him,
         const float* __restrict__ W1,  const float* __restrict__ b1,
         const float* __restrict__ W2,  const float* __restrict__ b2,
         const float* __restrict__ bias){
    __shared__ float s_acc[NB][4];
    __shared__ float s_cnt[NB];
    __shared__ bool  s_last;
    int t    = threadIdx.x;
    int lane = t & 31;
    if (t < NB*4) ((float*)s_acc)[t] = 0.0f;
    if (t < NB)   s_cnt[t] = 0.0f;
    __syncthreads();

    int b  = blockIdx.y;
    int g8 = blockIdx.x * blockDim.x + t;
    if (g8 < NG8) {
        int    n0   = g8 * 8;
        size_t base = ((size_t)b * CC) * (size_t)NN + (size_t)n0;

        float sl[8] = {0,0,0,0,0,0,0,0};
        float sh[8] = {0,0,0,0,0,0,0,0};

        // 8 groups of 8 channels; per group accumulate PRODUCT of (1+|z|) per
        // pixel slot, one lg2 per slot per group. Each thread handles 8
        // contiguous pixels => each warp reads 1KB contiguous per array per
        // channel (vs 512B before) for better DRAM page locality.
        for (int grp = 0; grp < 8; grp++){
            float pl[8] = {1,1,1,1,1,1,1,1};
            float ph[8] = {1,1,1,1,1,1,1,1};
            size_t off = base + (size_t)(grp * 8) * NN;
            #pragma unroll
            for (int cc = 0; cc < 8; cc++){
                const float4* pr0 = (const float4*)(lre + off);
                const float4* pi0 = (const float4*)(lim + off);
                float4 r0 = __ldcs(pr0),     i0 = __ldcs(pi0);
                float4 r1 = __ldcs(pr0 + 1), i1 = __ldcs(pi0 + 1);
                MAG8(pl, r0, i0, r1, i1)
                const float4* qr0 = (const float4*)(hre + off);
                const float4* qi0 = (const float4*)(him + off);
                float4 s0 = __ldcs(qr0),     j0 = __ldcs(qi0);
                float4 s1 = __ldcs(qr0 + 1), j1 = __ldcs(qi0 + 1);
                MAG8(ph, s0, j0, s1, j1)
                off += NN;
            }
            #pragma unroll
            for (int k = 0; k < 8; k++){
                sl[k] += f_lg2_approx(pl[k]);
                sh[k] += f_lg2_approx(ph[k]);
            }
        }

        const float sc = 0.69314718055994530942f / 64.0f;  // ln2 / C
        float dl[8], dh[8];
        #pragma unroll
        for (int k = 0; k < 8; k++){
            dl[k] = sl[k]*sc - XSHIFT;
            dh[k] = sh[k]*sc - XSHIFT;
        }

        int bd[8];
        #pragma unroll
        for (int k = 0; k < 8; k++) bd[k] = band_of(n0 + k);

        // side effect: persist the band table for k_write (batch 0 only)
        if (b == 0){
            g_bands4[g8*2]   = make_uchar4((unsigned char)bd[0], (unsigned char)bd[1],
                                           (unsigned char)bd[2], (unsigned char)bd[3]);
            g_bands4[g8*2+1] = make_uchar4((unsigned char)bd[4], (unsigned char)bd[5],
                                           (unsigned char)bd[6], (unsigned char)bd[7]);
        }

        bool merged = true;
        #pragma unroll
        for (int k = 1; k < 8; k++) merged &= (bd[k] == bd[0]);

        float s1l=0.f, s2l=0.f, s1h=0.f, s2h=0.f;
        #pragma unroll
        for (int k = 0; k < 8; k++){
            s1l += dl[k];  s2l += dl[k]*dl[k];
            s1h += dh[k];  s2h += dh[k]*dh[k];
        }

        const unsigned m = 0xffffffffu;
        int  bref = __shfl_sync(m, bd[0], 0);
        bool uni  = __all_sync(m, merged && (bd[0] == bref));

        if (uni){
            // whole warp (256 contiguous pixels) in one band: 4 atomics/warp
            #pragma unroll
            for (int o = 16; o > 0; o >>= 1){
                s1l += __shfl_xor_sync(m, s1l, o);
                s2l += __shfl_xor_sync(m, s2l, o);
                s1h += __shfl_xor_sync(m, s1h, o);
                s2h += __shfl_xor_sync(m, s2h, o);
            }
            if (lane == 0){
                atomicAdd(&s_acc[bref][0], s1l);
                atomicAdd(&s_acc[bref][1], s2l);
                atomicAdd(&s_acc[bref][2], s1h);
                atomicAdd(&s_acc[bref][3], s2h);
                if (b == 0) atomicAdd(&s_cnt[bref], 256.0f);
            }
        } else if (merged){
            atomicAdd(&s_acc[bd[0]][0], s1l);
            atomicAdd(&s_acc[bd[0]][1], s2l);
            atomicAdd(&s_acc[bd[0]][2], s1h);
            atomicAdd(&s_acc[bd[0]][3], s2h);
            if (b == 0) atomicAdd(&s_cnt[bd[0]], 8.0f);
        } else {
            #pragma unroll
            for (int k = 0; k < 8; k++){
                atomicAdd(&s_acc[bd[k]][0], dl[k]);
                atomicAdd(&s_acc[bd[k]][1], dl[k]*dl[k]);
                atomicAdd(&s_acc[bd[k]][2], dh[k]);
                atomicAdd(&s_acc[bd[k]][3], dh[k]*dh[k]);
                if (b == 0) atomicAdd(&s_cnt[bd[k]], 1.0f);
            }
        }
    }
    __syncthreads();

    // block -> global
    if (t < NB*4){
        int bd_ = t >> 2, q = t & 3;
        float v = s_acc[bd_][q];
        if (v != 0.0f) atomicAdd(&g_acc[b][bd_][q], v);
    }
    if (t < NB && b == 0){
        float v = s_cnt[t];
        if (v != 0.0f) atomicAdd(&g_cnt[t], v);
    }

    // last-block ticket: the final block runs the tiny MLP and resets state
    __threadfence();
    __syncthreads();
    if (t == 0){
        unsigned v = atomicAdd(&g_ticket, 1u);
        s_last = (v == (unsigned)(TOTAL_BLOCKS - 1));
    }
    __syncthreads();
    if (!s_last) return;

    __threadfence();  // acquire: make all blocks' atomics visible

    // Phase A: SNAPSHOT accumulators into registers.
    double cnt = 0.0, s1l = 0.0, s2l = 0.0, s1h = 0.0, s2h = 0.0;
    if (t < BB*NB){
        int bb = t >> 3, j = t & 7;
        cnt = (double)__ldcg(&g_cnt[j]);
        s1l = (double)__ldcg(&g_acc[bb][j][0]);
        s2l = (double)__ldcg(&g_acc[bb][j][1]);
        s1h = (double)__ldcg(&g_acc[bb][j][2]);
        s2h = (double)__ldcg(&g_acc[bb][j][3]);
    }

    // Phase B: barrier so no reset can precede any snapshot read.
    __syncthreads();

    // Phase C: reset scratch for the next graph replay.
    if (t < BB*NB*4) ((float*)g_acc)[t] = 0.0f;
    if (t < NB)      g_cnt[t] = 0.0f;
    if (t == 0)      g_ticket = 0u;

    // Phase D: MLP from registers only.
    if (t < BB*NB){
        int j = t & 7;
        double c1  = cnt < 1.0 ? 1.0 : cnt;
        double dml = s1l / c1, dmh = s1h / c1;
        double ml  = (double)XSHIFT + dml;
        double mh  = (double)XSHIFT + dmh;
        double vl  = s2l / c1 - dml*dml; if (vl < 0.0) vl = 0.0;
        double vh  = s2h / c1 - dmh*dmh; if (vh < 0.0) vh = 0.0;

        float fe0 = fixf((float)ml);
        float fe1 = fixf((float)mh);
        float fe2 = fixf((float)sqrt(vl));
        float fe3 = fixf((float)sqrt(vh));

        float acc = b2[0] + bias[j];
        #pragma unroll
        for (int i = 0; i < 32; i++){
            float a = b1[i];
            a += fe0*W1[i*4+0];
            a += fe1*W1[i*4+1];
            a += fe2*W1[i*4+2];
            a += fe3*W1[i*4+3];
            float gl = 0.5f * a * (1.0f + erff(a * 0.70710678118654752440f));
            acc += gl * W2[i];
        }
        g_alpha[t] = 1.0f / (1.0f + expf(-acc));
    }
}

// table-driven alpha broadcast: one gather + one float4 store per thread
__global__ void __launch_bounds__(256)
k_write(float* __restrict__ out){
    __shared__ float s_alpha[NB];
    int b = blockIdx.y;
    if (threadIdx.x < NB) s_alpha[threadIdx.x] = g_alpha[b * NB + threadIdx.x];
    __syncthreads();

    int g = blockIdx.x * blockDim.x + threadIdx.x;
    if (g >= NG) return;
    uchar4 tb = g_bands4[g];
    float4 v;
    v.x = s_alpha[tb.x];
    v.y = s_alpha[tb.y];
    v.z = s_alpha[tb.z];
    v.w = s_alpha[tb.w];
    ((float4*)(out + (size_t)b * NN))[g] = v;
}

extern "C" void kernel_launch(void* const* d_in, const int* in_sizes, int n_in,
                              void* d_out, int out_size){
    const float* lre  = (const float*)d_in[0];
    const float* lim  = (const float*)d_in[1];
    const float* hre  = (const float*)d_in[2];
    const float* him  = (const float*)d_in[3];
    const float* W1   = (const float*)d_in[4];
    const float* b1   = (const float*)d_in[5];
    const float* W2   = (const float*)d_in[6];
    const float* b2   = (const float*)d_in[7];
    const float* bias = (const float*)d_in[8];
    float* out = (float*)d_out;

    dim3 rgrid(GX8, BB);
    k_reduce<<<rgrid, 256>>>(lre, lim, hre, him, W1, b1, W2, b2, bias);
    dim3 wgrid((NG + 255) / 256, BB);
    k_write<<<wgrid, 256>>>(out);
}

// round 10
// speedup vs baseline: 1.2444x; 1.2444x over previous
#include <cuda_runtime.h>
#include <math.h>

#define NB  8
#define CC  64
#define HH  512
#define WW  257
#define BB  8
#define NN  (HH*WW)      // 131584
#define NG  (NN/4)       // 32896 float4 groups per batch
#define GX  ((NG + 255) / 256)     // 129 blocks in x
#define TOTAL_BLOCKS (GX * BB * 2) // 2064 (x2 for low/high split)

// Device-global scratch (no cudaMalloc allowed). Zero at module load; the
// fused MLP phase snapshots then resets everything, so each graph replay
// starts from a clean state. g_bands4 is rewritten identically every call.
__device__ float        g_acc[BB][NB][4];  // [b][band][S1_low,S2_low,S1_high,S2_high]
__device__ float        g_cnt[NB];
__device__ float        g_alpha[BB*NB];
__device__ unsigned int g_ticket;
__device__ uchar4       g_bands4[NG];      // band ids per float4 group

#define XSHIFT 0.8f   // x = mean-over-channels log1p(|z|) is ~0.81 +- 0.05

__device__ __forceinline__ float f_sqrt_approx(float x){
    float r; asm("sqrt.approx.f32 %0, %1;" : "=f"(r) : "f"(x)); return r;
}
__device__ __forceinline__ float f_lg2_approx(float x){
    float r; asm("lg2.approx.f32 %0, %1;" : "=f"(r) : "f"(x)); return r;
}

// Exact replication of the reference band assignment (bit-identical fp32 ops).
__device__ __forceinline__ int band_of(int n){
    int iy = n / WW;
    int ix = n - iy * WW;
    float fy = (float)(iy < 256 ? iy : iy - 512) * (1.0f/512.0f);
    float fx = (float)ix * (1.0f/512.0f);
    float r  = __fsqrt_rn(fx*fx + fy*fy);
    float rn = __fdiv_rn(r, 0.70710678118654752440f);
    int band = (rn > 0.125f) + (rn > 0.25f) + (rn > 0.375f) + (rn > 0.5f)
             + (rn > 0.625f) + (rn > 0.75f) + (rn > 0.875f);
    return band;
}

__device__ __forceinline__ float fixf(float x){
    if (isnan(x)) return 0.0f;
    if (isinf(x)) return x > 0.f ? 50.0f : -50.0f;
    return x;
}

__global__ void __launch_bounds__(256)
k_reduce(const float* __restrict__ lre, const float* __restrict__ lim,
         const float* __restrict__ hre, const float* __restrict__ him,
         const float* __restrict__ W1,  const float* __restrict__ b1,
         const float* __restrict__ W2,  const float* __restrict__ b2,
         const float* __restrict__ bias){
    __shared__ float s_acc[NB][2];   // this block's (batch, half) accumulators
    __shared__ float s_cnt[NB];
    __shared__ bool  s_last;
    int t    = threadIdx.x;
    int lane = t & 31;
    if (t < NB*2) ((float*)s_acc)[t] = 0.0f;
    if (t < NB)   s_cnt[t] = 0.0f;
    __syncthreads();

    int b    = blockIdx.y;
    int half = blockIdx.z;           // 0 = low pair, 1 = high pair
    const float* re = half ? hre : lre;
    const float* im = half ? him : lim;

    int g = blockIdx.x * blockDim.x + t;
    if (g < NG) {
        size_t base = ((size_t)b * CC) * (size_t)NN + (size_t)(g * 4);

        float s0=0.f, s1_=0.f, s2_=0.f, s3=0.f;

        // 8 groups of 8 channels; per group accumulate PRODUCT of (1+|z|) per
        // pixel slot, then one lg2 per slot per group (8x fewer MUFU lg2).
        // Only 2 load streams per warp (re, im) and 4 live products: lower
        // register pressure and longer effective per-stream runs than the
        // 4-stream variant.
        for (int grp = 0; grp < 8; grp++){
            float p0=1.f, p1=1.f, p2=1.f, p3=1.f;
            size_t off = base + (size_t)(grp * 8) * NN;
            #pragma unroll
            for (int cc = 0; cc < 8; cc++){
                float4 vr = __ldcs((const float4*)(re + off));
                float4 vi = __ldcs((const float4*)(im + off));
                off += NN;
                p0 *= 1.0f + f_sqrt_approx(vr.x*vr.x + vi.x*vi.x);
                p1 *= 1.0f + f_sqrt_approx(vr.y*vr.y + vi.y*vi.y);
                p2 *= 1.0f + f_sqrt_approx(vr.z*vr.z + vi.z*vi.z);
                p3 *= 1.0f + f_sqrt_approx(vr.w*vr.w + vi.w*vi.w);
            }
            s0  += f_lg2_approx(p0);
            s1_ += f_lg2_approx(p1);
            s2_ += f_lg2_approx(p2);
            s3  += f_lg2_approx(p3);
        }

        const float sc = 0.69314718055994530942f / 64.0f;  // ln2 / C
        float d0 = s0*sc  - XSHIFT, d1 = s1_*sc - XSHIFT;
        float d2 = s2_*sc - XSHIFT, d3 = s3*sc  - XSHIFT;

        int n0 = g * 4;
        int b0 = band_of(n0+0), b1_ = band_of(n0+1), b2_ = band_of(n0+2), b3_ = band_of(n0+3);
        bool merged = (b0 == b1_) && (b0 == b2_) && (b0 == b3_);

        // side effect: persist band table for k_write (one writer set only)
        if (b == 0 && half == 0){
            g_bands4[g] = make_uchar4((unsigned char)b0, (unsigned char)b1_,
                                      (unsigned char)b2_, (unsigned char)b3_);
        }

        float S1 = d0+d1+d2+d3;
        float S2 = d0*d0+d1*d1+d2*d2+d3*d3;

        const unsigned m = 0xffffffffu;
        int  bref = __shfl_sync(m, b0, 0);
        bool uni  = __all_sync(m, merged && (b0 == bref));

        if (uni){
            // whole warp in one band: butterfly-reduce, 2 atomics per WARP
            #pragma unroll
            for (int o = 16; o > 0; o >>= 1){
                S1 += __shfl_xor_sync(m, S1, o);
                S2 += __shfl_xor_sync(m, S2, o);
            }
            if (lane == 0){
                atomicAdd(&s_acc[bref][0], S1);
                atomicAdd(&s_acc[bref][1], S2);
                if (b == 0 && half == 0) atomicAdd(&s_cnt[bref], 128.0f);
            }
        } else if (merged){
            atomicAdd(&s_acc[b0][0], S1);
            atomicAdd(&s_acc[b0][1], S2);
            if (b == 0 && half == 0) atomicAdd(&s_cnt[b0], 4.0f);
        } else {
            int   bd[4] = { b0, b1_, b2_, b3_ };
            float dd[4] = { d0, d1, d2, d3 };
            #pragma unroll
            for (int k = 0; k < 4; k++){
                atomicAdd(&s_acc[bd[k]][0], dd[k]);
                atomicAdd(&s_acc[bd[k]][1], dd[k]*dd[k]);
                if (b == 0 && half == 0) atomicAdd(&s_cnt[bd[k]], 1.0f);
            }
        }
    }
    __syncthreads();

    // block -> global: slot [half*2 + q]
    if (t < NB*2){
        int bd = t >> 1, q = t & 1;
        float v = s_acc[bd][q];
        if (v != 0.0f) atomicAdd(&g_acc[b][bd][half*2 + q], v);
    }
    if (t < NB && b == 0 && half == 0){
        float v = s_cnt[t];
        if (v != 0.0f) atomicAdd(&g_cnt[t], v);
    }

    // last-block ticket: the final block runs the tiny MLP and resets state
    __threadfence();
    __syncthreads();
    if (t == 0){
        unsigned v = atomicAdd(&g_ticket, 1u);
        s_last = (v == (unsigned)(TOTAL_BLOCKS - 1));
    }
    __syncthreads();
    if (!s_last) return;

    __threadfence();  // acquire: make all blocks' atomics visible

    // Phase A: SNAPSHOT accumulators into registers.
    double cnt = 0.0, s1l = 0.0, s2l = 0.0, s1h = 0.0, s2h = 0.0;
    if (t < BB*NB){
        int bb = t >> 3, j = t & 7;
        cnt = (double)__ldcg(&g_cnt[j]);
        s1l = (double)__ldcg(&g_acc[bb][j][0]);
        s2l = (double)__ldcg(&g_acc[bb][j][1]);
        s1h = (double)__ldcg(&g_acc[bb][j][2]);
        s2h = (double)__ldcg(&g_acc[bb][j][3]);
    }

    // Phase B: barrier so no reset can precede any snapshot read.
    __syncthreads();

    // Phase C: reset scratch for the next graph replay.
    if (t < BB*NB*4) ((float*)g_acc)[t] = 0.0f;
    if (t < NB)      g_cnt[t] = 0.0f;
    if (t == 0)      g_ticket = 0u;

    // Phase D: MLP from registers only.
    if (t < BB*NB){
        int j = t & 7;
        double c1  = cnt < 1.0 ? 1.0 : cnt;
        double dml = s1l / c1, dmh = s1h / c1;
        double ml  = (double)XSHIFT + dml;
        double mh  = (double)XSHIFT + dmh;
        double vl  = s2l / c1 - dml*dml; if (vl < 0.0) vl = 0.0;
        double vh  = s2h / c1 - dmh*dmh; if (vh < 0.0) vh = 0.0;

        float fe0 = fixf((float)ml);
        float fe1 = fixf((float)mh);
        float fe2 = fixf((float)sqrt(vl));
        float fe3 = fixf((float)sqrt(vh));

        float acc = b2[0] + bias[j];
        #pragma unroll
        for (int i = 0; i < 32; i++){
            float a = b1[i];
            a += fe0*W1[i*4+0];
            a += fe1*W1[i*4+1];
            a += fe2*W1[i*4+2];
            a += fe3*W1[i*4+3];
            float gl = 0.5f * a * (1.0f + erff(a * 0.70710678118654752440f));
            acc += gl * W2[i];
        }
        g_alpha[t] = 1.0f / (1.0f + expf(-acc));
    }
}

// table-driven alpha broadcast: one gather + one float4 store per thread
__global__ void __launch_bounds__(256)
k_write(float* __restrict__ out){
    __shared__ float s_alpha[NB];
    int b = blockIdx.y;
    if (threadIdx.x < NB) s_alpha[threadIdx.x] = g_alpha[b * NB + threadIdx.x];
    __syncthreads();

    int g = blockIdx.x * blockDim.x + threadIdx.x;
    if (g >= NG) return;
    uchar4 tb = g_bands4[g];
    float4 v;
    v.x = s_alpha[tb.x];
    v.y = s_alpha[tb.y];
    v.z = s_alpha[tb.z];
    v.w = s_alpha[tb.w];
    ((float4*)(out + (size_t)b * NN))[g] = v;
}

extern "C" void kernel_launch(void* const* d_in, const int* in_sizes, int n_in,
                              void* d_out, int out_size){
    const float* lre  = (const float*)d_in[0];
    const float* lim  = (const float*)d_in[1];
    const float* hre  = (const float*)d_in[2];
    const float* him  = (const float*)d_in[3];
    const float* W1   = (const float*)d_in[4];
    const float* b1   = (const float*)d_in[5];
    const float* W2   = (const float*)d_in[6];
    const float* b2   = (const float*)d_in[7];
    const float* bias = (const float*)d_in[8];
    float* out = (float*)d_out;

    dim3 rgrid(GX, BB, 2);
    k_reduce<<<rgrid, 256>>>(lre, lim, hre, him, W1, b1, W2, b2, bias);
    dim3 wgrid(GX, BB);
    k_write<<<wgrid, 256>>>(out);
}

// round 14
// speedup vs baseline: 1.2545x; 1.0081x over previous
#include <cuda_runtime.h>
#include <math.h>

#define NB  8
#define CC  64
#define HH  512
#define WW  257
#define BB  8
#define NN  (HH*WW)      // 131584
#define NG  (NN/4)       // 32896 float4 groups per batch
#define RBT 128                       // k_reduce block threads
#define GX  ((NG + RBT - 1) / RBT)    // 257 blocks in x
#define TOTAL_BLOCKS (GX * BB * 2)    // 4112 (x2 for low/high split)

// Device-global scratch (no cudaMalloc allowed). Zero at module load; the
// fused MLP phase snapshots then resets everything, so each graph replay
// starts from a clean state. g_bands4 is rewritten identically every call.
__device__ float        g_acc[BB][NB][4];  // [b][band][S1_low,S2_low,S1_high,S2_high]
__device__ float        g_cnt[NB];
__device__ float        g_alpha[BB*NB];
__device__ unsigned int g_ticket;
__device__ uchar4       g_bands4[NG];      // band ids per float4 group

#define XSHIFT 0.8f   // x = mean-over-channels log1p(|z|) is ~0.81 +- 0.05

__device__ __forceinline__ float f_sqrt_approx(float x){
    float r; asm("sqrt.approx.f32 %0, %1;" : "=f"(r) : "f"(x)); return r;
}
__device__ __forceinline__ float f_lg2_approx(float x){
    float r; asm("lg2.approx.f32 %0, %1;" : "=f"(r) : "f"(x)); return r;
}

// Exact replication of the reference band assignment (bit-identical fp32 ops).
__device__ __forceinline__ int band_of(int n){
    int iy = n / WW;
    int ix = n - iy * WW;
    float fy = (float)(iy < 256 ? iy : iy - 512) * (1.0f/512.0f);
    float fx = (float)ix * (1.0f/512.0f);
    float r  = __fsqrt_rn(fx*fx + fy*fy);
    float rn = __fdiv_rn(r, 0.70710678118654752440f);
    int band = (rn > 0.125f) + (rn > 0.25f) + (rn > 0.375f) + (rn > 0.5f)
             + (rn > 0.625f) + (rn > 0.75f) + (rn > 0.875f);
    return band;
}

__device__ __forceinline__ float fixf(float x){
    if (isnan(x)) return 0.0f;
    if (isinf(x)) return x > 0.f ? 50.0f : -50.0f;
    return x;
}

__global__ void __launch_bounds__(RBT)
k_reduce(const float* __restrict__ lre, const float* __restrict__ lim,
         const float* __restrict__ hre, const float* __restrict__ him,
         const float* __restrict__ W1,  const float* __restrict__ b1,
         const float* __restrict__ W2,  const float* __restrict__ b2,
         const float* __restrict__ bias){
    __shared__ float s_acc[NB][2];   // this block's (batch, half) accumulators
    __shared__ float s_cnt[NB];
    __shared__ bool  s_last;
    int t    = threadIdx.x;
    int lane = t & 31;
    if (t < NB*2) ((float*)s_acc)[t] = 0.0f;
    if (t < NB)   s_cnt[t] = 0.0f;
    __syncthreads();

    int b    = blockIdx.y;
    int half = blockIdx.z;           // 0 = low pair, 1 = high pair
    const float* re = half ? hre : lre;
    const float* im = half ? him : lim;

    int g = blockIdx.x * RBT + t;
    if (g < NG) {
        size_t base = ((size_t)b * CC) * (size_t)NN + (size_t)(g * 4);

        float s0=0.f, s1_=0.f, s2_=0.f, s3=0.f;

        // 8 groups of 8 channels; per group accumulate PRODUCT of (1+|z|) per
        // pixel slot, then one lg2 per slot per group (8x fewer MUFU lg2).
        // Only 2 load streams per warp and 4 live products.
        for (int grp = 0; grp < 8; grp++){
            float p0=1.f, p1=1.f, p2=1.f, p3=1.f;
            size_t off = base + (size_t)(grp * 8) * NN;
            #pragma unroll
            for (int cc = 0; cc < 8; cc++){
                float4 vr = __ldcs((const float4*)(re + off));
                float4 vi = __ldcs((const float4*)(im + off));
                off += NN;
                p0 *= 1.0f + f_sqrt_approx(vr.x*vr.x + vi.x*vi.x);
                p1 *= 1.0f + f_sqrt_approx(vr.y*vr.y + vi.y*vi.y);
                p2 *= 1.0f + f_sqrt_approx(vr.z*vr.z + vi.z*vi.z);
                p3 *= 1.0f + f_sqrt_approx(vr.w*vr.w + vi.w*vi.w);
            }
            s0  += f_lg2_approx(p0);
            s1_ += f_lg2_approx(p1);
            s2_ += f_lg2_approx(p2);
            s3  += f_lg2_approx(p3);
        }

        const float sc = 0.69314718055994530942f / 64.0f;  // ln2 / C
        float d0 = s0*sc  - XSHIFT, d1 = s1_*sc - XSHIFT;
        float d2 = s2_*sc - XSHIFT, d3 = s3*sc  - XSHIFT;

        int n0 = g * 4;
        int b0 = band_of(n0+0), b1_ = band_of(n0+1), b2_ = band_of(n0+2), b3_ = band_of(n0+3);
        bool merged = (b0 == b1_) && (b0 == b2_) && (b0 == b3_);

        // side effect: persist band table for k_write (one writer set only)
        if (b == 0 && half == 0){
            g_bands4[g] = make_uchar4((unsigned char)b0, (unsigned char)b1_,
                                      (unsigned char)b2_, (unsigned char)b3_);
        }

        float S1 = d0+d1+d2+d3;
        float S2 = d0*d0+d1*d1+d2*d2+d3*d3;

        const unsigned m = 0xffffffffu;
        int  bref = __shfl_sync(m, b0, 0);
        bool uni  = __all_sync(m, merged && (b0 == bref));

        if (uni){
            // whole warp in one band: butterfly-reduce, 2 atomics per WARP
            #pragma unroll
            for (int o = 16; o > 0; o >>= 1){
                S1 += __shfl_xor_sync(m, S1, o);
                S2 += __shfl_xor_sync(m, S2, o);
            }
            if (lane == 0){
                atomicAdd(&s_acc[bref][0], S1);
                atomicAdd(&s_acc[bref][1], S2);
                if (b == 0 && half == 0) atomicAdd(&s_cnt[bref], 128.0f);
            }
        } else if (merged){
            atomicAdd(&s_acc[b0][0], S1);
            atomicAdd(&s_acc[b0][1], S2);
            if (b == 0 && half == 0) atomicAdd(&s_cnt[b0], 4.0f);
        } else {
            int   bd[4] = { b0, b1_, b2_, b3_ };
            float dd[4] = { d0, d1, d2, d3 };
            #pragma unroll
            for (int k = 0; k < 4; k++){
                atomicAdd(&s_acc[bd[k]][0], dd[k]);
                atomicAdd(&s_acc[bd[k]][1], dd[k]*dd[k]);
                if (b == 0 && half == 0) atomicAdd(&s_cnt[bd[k]], 1.0f);
            }
        }
    }
    __syncthreads();

    // block -> global: slot [half*2 + q]
    if (t < NB*2){
        int bd = t >> 1, q = t & 1;
        float v = s_acc[bd][q];
        if (v != 0.0f) atomicAdd(&g_acc[b][bd][half*2 + q], v);
    }
    if (t < NB && b == 0 && half == 0){
        float v = s_cnt[t];
        if (v != 0.0f) atomicAdd(&g_cnt[t], v);
    }

    // last-block ticket: the final block runs the tiny MLP and resets state
    __threadfence();
    __syncthreads();
    if (t == 0){
        unsigned v = atomicAdd(&g_ticket, 1u);
        s_last = (v == (unsigned)(TOTAL_BLOCKS - 1));
    }
    __syncthreads();
    if (!s_last) return;

    __threadfence();  // acquire: make all blocks' atomics visible

    // Phase A: SNAPSHOT accumulators into registers (t < 64 covers all).
    double cnt = 0.0, s1l = 0.0, s2l = 0.0, s1h = 0.0, s2h = 0.0;
    if (t < BB*NB){
        int bb = t >> 3, j = t & 7;
        cnt = (double)__ldcg(&g_cnt[j]);
        s1l = (double)__ldcg(&g_acc[bb][j][0]);
        s2l = (double)__ldcg(&g_acc[bb][j][1]);
        s1h = (double)__ldcg(&g_acc[bb][j][2]);
        s2h = (double)__ldcg(&g_acc[bb][j][3]);
    }

    // Phase B: barrier so no reset can precede any snapshot read.
    __syncthreads();

    // Phase C: reset scratch for the next graph replay (256 entries, RBT=128
    // threads -> loop).
    for (int i = t; i < BB*NB*4; i += RBT) ((float*)g_acc)[i] = 0.0f;
    if (t < NB) g_cnt[t] = 0.0f;
    if (t == 0) g_ticket = 0u;

    // Phase D: MLP from registers only.
    if (t < BB*NB){
        int j = t & 7;
        double c1  = cnt < 1.0 ? 1.0 : cnt;
        double dml = s1l / c1, dmh = s1h / c1;
        double ml  = (double)XSHIFT + dml;
        double mh  = (double)XSHIFT + dmh;
        double vl  = s2l / c1 - dml*dml; if (vl < 0.0) vl = 0.0;
        double vh  = s2h / c1 - dmh*dmh; if (vh < 0.0) vh = 0.0;

        float fe0 = fixf((float)ml);
        float fe1 = fixf((float)mh);
        float fe2 = fixf((float)sqrt(vl));
        float fe3 = fixf((float)sqrt(vh));

        float acc = b2[0] + bias[j];
        #pragma unroll
        for (int i = 0; i < 32; i++){
            float a = b1[i];
            a += fe0*W1[i*4+0];
            a += fe1*W1[i*4+1];
            a += fe2*W1[i*4+2];
            a += fe3*W1[i*4+3];
            float gl = 0.5f * a * (1.0f + erff(a * 0.70710678118654752440f));
            acc += gl * W2[i];
        }
        g_alpha[t] = 1.0f / (1.0f + expf(-acc));
    }
}

// table-driven alpha broadcast: 2 groups per thread, streaming stores
#define WPT 2
__global__ void __launch_bounds__(256)
k_write(float* __restrict__ out){
    __shared__ float s_alpha[NB];
    int b = blockIdx.y;
    if (threadIdx.x < NB) s_alpha[threadIdx.x] = g_alpha[b * NB + threadIdx.x];
    __syncthreads();

    float4* ob = (float4*)(out + (size_t)b * NN);
    int g0 = blockIdx.x * (256 * WPT) + threadIdx.x;
    #pragma unroll
    for (int w = 0; w < WPT; w++){
        int g = g0 + w * 256;
        if (g < NG){
            uchar4 tb = g_bands4[g];
            float4 v;
            v.x = s_alpha[tb.x];
            v.y = s_alpha[tb.y];
            v.z = s_alpha[tb.z];
            v.w = s_alpha[tb.w];
            __stcs(&ob[g], v);
        }
    }
}

extern "C" void kernel_launch(void* const* d_in, const int* in_sizes, int n_in,
                              void* d_out, int out_size){
    const float* lre  = (const float*)d_in[0];
    const float* lim  = (const float*)d_in[1];
    const float* hre  = (const float*)d_in[2];
    const float* him  = (const float*)d_in[3];
    const float* W1   = (const float*)d_in[4];
    const float* b1   = (const float*)d_in[5];
    const float* W2   = (const float*)d_in[6];
    const float* b2   = (const float*)d_in[7];
    const float* bias = (const float*)d_in[8];
    float* out = (float*)d_out;

    dim3 rgrid(GX, BB, 2);
    k_reduce<<<rgrid, RBT>>>(lre, lim, hre, him, W1, b1, W2, b2, bias);
    dim3 wgrid((NG + 256*WPT - 1) / (256*WPT), BB);
    k_write<<<wgrid, 256>>>(out);
}

// round 16
// speedup vs baseline: 1.2780x; 1.0188x over previous
#include <cuda_runtime.h>
#include <math.h>

#define NB  8
#define CC  64
#define HH  512
#define WW  257
#define BB  8
#define NN  (HH*WW)      // 131584
#define NG  (NN/4)       // 32896 float4 groups per batch
#define NG8 (NN/8)       // 16448 8-pixel units per batch
#define RBT 128                          // k_reduce block threads
#define GX8 ((NG8 + RBT - 1) / RBT)      // 129 blocks in x
#define TOTAL_BLOCKS (GX8 * BB * 2)      // 2064 (x2 for low/high split)

// Device-global scratch (no cudaMalloc allowed). Zero at module load; the
// fused MLP phase snapshots then resets everything, so each graph replay
// starts from a clean state. g_bands4 is rewritten identically every call.
__device__ float        g_acc[BB][NB][4];  // [b][band][S1_low,S2_low,S1_high,S2_high]
__device__ float        g_cnt[NB];
__device__ float        g_alpha[BB*NB];
__device__ unsigned int g_ticket;
__device__ uchar4       g_bands4[NG];      // band ids per float4 group

#define XSHIFT 0.8f   // x = mean-over-channels log1p(|z|) is ~0.81 +- 0.05

__device__ __forceinline__ float f_sqrt_approx(float x){
    float r; asm("sqrt.approx.f32 %0, %1;" : "=f"(r) : "f"(x)); return r;
}
__device__ __forceinline__ float f_lg2_approx(float x){
    float r; asm("lg2.approx.f32 %0, %1;" : "=f"(r) : "f"(x)); return r;
}

// Exact replication of the reference band assignment (bit-identical fp32 ops).
__device__ __forceinline__ int band_of(int n){
    int iy = n / WW;
    int ix = n - iy * WW;
    float fy = (float)(iy < 256 ? iy : iy - 512) * (1.0f/512.0f);
    float fx = (float)ix * (1.0f/512.0f);
    float r  = __fsqrt_rn(fx*fx + fy*fy);
    float rn = __fdiv_rn(r, 0.70710678118654752440f);
    int band = (rn > 0.125f) + (rn > 0.25f) + (rn > 0.375f) + (rn > 0.5f)
             + (rn > 0.625f) + (rn > 0.75f) + (rn > 0.875f);
    return band;
}

__device__ __forceinline__ float fixf(float x){
    if (isnan(x)) return 0.0f;
    if (isinf(x)) return x > 0.f ? 50.0f : -50.0f;
    return x;
}

__global__ void __launch_bounds__(RBT)
k_reduce(const float* __restrict__ lre, const float* __restrict__ lim,
         const float* __restrict__ hre, const float* __restrict__ him,
         const float* __restrict__ W1,  const float* __restrict__ b1,
         const float* __restrict__ W2,  const float* __restrict__ b2,
         const float* __restrict__ bias){
    __shared__ float s_acc[NB][2];   // this block's (batch, half) accumulators
    __shared__ float s_cnt[NB];
    __shared__ bool  s_last;
    int t    = threadIdx.x;
    int lane = t & 31;
    if (t < NB*2) ((float*)s_acc)[t] = 0.0f;
    if (t < NB)   s_cnt[t] = 0.0f;
    __syncthreads();

    int b    = blockIdx.y;
    int half = blockIdx.z;           // 0 = low pair, 1 = high pair
    const float* re = half ? hre : lre;
    const float* im = half ? him : lim;

    int g8 = blockIdx.x * RBT + t;   // NG8 % 32 == 0 -> warp-uniform guard
    if (g8 < NG8) {
        int    n0   = g8 * 8;
        size_t base = ((size_t)b * CC) * (size_t)NN + (size_t)n0;

        float s[8] = {0,0,0,0,0,0,0,0};

        // 8 groups of 8 channels; per group accumulate PRODUCT of (1+|z|) per
        // pixel slot, one lg2 per slot per group. 8 contiguous pixels per
        // thread on a single (re,im) stream pair: each warp reads 1KB
        // contiguous per stream per channel; only 8 products + 8 sums live.
        for (int grp = 0; grp < 8; grp++){
            float p[8] = {1,1,1,1,1,1,1,1};
            size_t off = base + (size_t)(grp * 8) * NN;
            #pragma unroll
            for (int cc = 0; cc < 8; cc++){
                const float4* pr = (const float4*)(re + off);
                const float4* pi = (const float4*)(im + off);
                float4 r0 = __ldcs(pr),     i0 = __ldcs(pi);
                float4 r1 = __ldcs(pr + 1), i1 = __ldcs(pi + 1);
                off += NN;
                p[0] *= 1.0f + f_sqrt_approx(r0.x*r0.x + i0.x*i0.x);
                p[1] *= 1.0f + f_sqrt_approx(r0.y*r0.y + i0.y*i0.y);
                p[2] *= 1.0f + f_sqrt_approx(r0.z*r0.z + i0.z*i0.z);
                p[3] *= 1.0f + f_sqrt_approx(r0.w*r0.w + i0.w*i0.w);
                p[4] *= 1.0f + f_sqrt_approx(r1.x*r1.x + i1.x*i1.x);
                p[5] *= 1.0f + f_sqrt_approx(r1.y*r1.y + i1.y*i1.y);
                p[6] *= 1.0f + f_sqrt_approx(r1.z*r1.z + i1.z*i1.z);
                p[7] *= 1.0f + f_sqrt_approx(r1.w*r1.w + i1.w*i1.w);
            }
            #pragma unroll
            for (int k = 0; k < 8; k++) s[k] += f_lg2_approx(p[k]);
        }

        const float sc = 0.69314718055994530942f / 64.0f;  // ln2 / C
        float d[8];
        #pragma unroll
        for (int k = 0; k < 8; k++) d[k] = s[k]*sc - XSHIFT;

        int bd[8];
        #pragma unroll
        for (int k = 0; k < 8; k++) bd[k] = band_of(n0 + k);

        // side effect: persist band table for k_write (one writer set only)
        if (b == 0 && half == 0){
            g_bands4[g8*2]   = make_uchar4((unsigned char)bd[0], (unsigned char)bd[1],
                                           (unsigned char)bd[2], (unsigned char)bd[3]);
            g_bands4[g8*2+1] = make_uchar4((unsigned char)bd[4], (unsigned char)bd[5],
                                           (unsigned char)bd[6], (unsigned char)bd[7]);
        }

        bool merged = true;
        #pragma unroll
        for (int k = 1; k < 8; k++) merged &= (bd[k] == bd[0]);

        float S1 = 0.f, S2 = 0.f;
        #pragma unroll
        for (int k = 0; k < 8; k++){ S1 += d[k]; S2 += d[k]*d[k]; }

        const unsigned m = 0xffffffffu;
        int  bref = __shfl_sync(m, bd[0], 0);
        bool uni  = __all_sync(m, merged && (bd[0] == bref));

        if (uni){
            // whole warp (256 contiguous pixels) in one band: 2 atomics/warp
            #pragma unroll
            for (int o = 16; o > 0; o >>= 1){
                S1 += __shfl_xor_sync(m, S1, o);
                S2 += __shfl_xor_sync(m, S2, o);
            }
            if (lane == 0){
                atomicAdd(&s_acc[bref][0], S1);
                atomicAdd(&s_acc[bref][1], S2);
                if (b == 0 && half == 0) atomicAdd(&s_cnt[bref], 256.0f);
            }
        } else if (merged){
            atomicAdd(&s_acc[bd[0]][0], S1);
            atomicAdd(&s_acc[bd[0]][1], S2);
            if (b == 0 && half == 0) atomicAdd(&s_cnt[bd[0]], 8.0f);
        } else {
            #pragma unroll
            for (int k = 0; k < 8; k++){
                atomicAdd(&s_acc[bd[k]][0], d[k]);
                atomicAdd(&s_acc[bd[k]][1], d[k]*d[k]);
                if (b == 0 && half == 0) atomicAdd(&s_cnt[bd[k]], 1.0f);
            }
        }
    }
    __syncthreads();

    // block -> global: slot [half*2 + q]
    if (t < NB*2){
        int bd_ = t >> 1, q = t & 1;
        float v = s_acc[bd_][q];
        if (v != 0.0f) atomicAdd(&g_acc[b][bd_][half*2 + q], v);
    }
    if (t < NB && b == 0 && half == 0){
        float v = s_cnt[t];
        if (v != 0.0f) atomicAdd(&g_cnt[t], v);
    }

    // last-block ticket: the final block runs the tiny MLP and resets state
    __threadfence();
    __syncthreads();
    if (t == 0){
        unsigned v = atomicAdd(&g_ticket, 1u);
        s_last = (v == (unsigned)(TOTAL_BLOCKS - 1));
    }
    __syncthreads();
    if (!s_last) return;

    __threadfence();  // acquire: make all blocks' atomics visible

    // Phase A: SNAPSHOT accumulators into registers.
    double cnt = 0.0, s1l = 0.0, s2l = 0.0, s1h = 0.0, s2h = 0.0;
    if (t < BB*NB){
        int bb = t >> 3, j = t & 7;
        cnt = (double)__ldcg(&g_cnt[j]);
        s1l = (double)__ldcg(&g_acc[bb][j][0]);
        s2l = (double)__ldcg(&g_acc[bb][j][1]);
        s1h = (double)__ldcg(&g_acc[bb][j][2]);
        s2h = (double)__ldcg(&g_acc[bb][j][3]);
    }

    // Phase B: barrier so no reset can precede any snapshot read.
    __syncthreads();

    // Phase C: reset scratch for the next graph replay.
    for (int i = t; i < BB*NB*4; i += RBT) ((float*)g_acc)[i] = 0.0f;
    if (t < NB) g_cnt[t] = 0.0f;
    if (t == 0) g_ticket = 0u;

    // Phase D: MLP from registers only.
    if (t < BB*NB){
        int j = t & 7;
        double c1  = cnt < 1.0 ? 1.0 : cnt;
        double dml = s1l / c1, dmh = s1h / c1;
        double ml  = (double)XSHIFT + dml;
        double mh  = (double)XSHIFT + dmh;
        double vl  = s2l / c1 - dml*dml; if (vl < 0.0) vl = 0.0;
        double vh  = s2h / c1 - dmh*dmh; if (vh < 0.0) vh = 0.0;

        float fe0 = fixf((float)ml);
        float fe1 = fixf((float)mh);
        float fe2 = fixf((float)sqrt(vl));
        float fe3 = fixf((float)sqrt(vh));

        float acc = b2[0] + bias[j];
        #pragma unroll
        for (int i = 0; i < 32; i++){
            float a = b1[i];
            a += fe0*W1[i*4+0];
            a += fe1*W1[i*4+1];
            a += fe2*W1[i*4+2];
            a += fe3*W1[i*4+3];
            float gl = 0.5f * a * (1.0f + erff(a * 0.70710678118654752440f));
            acc += gl * W2[i];
        }
        g_alpha[t] = 1.0f / (1.0f + expf(-acc));
    }
}

// table-driven alpha broadcast: R10's measured-fastest config (4.7us)
__global__ void __launch_bounds__(256)
k_write(float* __restrict__ out){
    __shared__ float s_alpha[NB];
    int b = blockIdx.y;
    if (threadIdx.x < NB) s_alpha[threadIdx.x] = g_alpha[b * NB + threadIdx.x];
    __syncthreads();

    int g = blockIdx.x * blockDim.x + threadIdx.x;
    if (g >= NG) return;
    uchar4 tb = g_bands4[g];
    float4 v;
    v.x = s_alpha[tb.x];
    v.y = s_alpha[tb.y];
    v.z = s_alpha[tb.z];
    v.w = s_alpha[tb.w];
    ((float4*)(out + (size_t)b * NN))[g] = v;
}

extern "C" void kernel_launch(void* const* d_in, const int* in_sizes, int n_in,
                              void* d_out, int out_size){
    const float* lre  = (const float*)d_in[0];
    const float* lim  = (const float*)d_in[1];
    const float* hre  = (const float*)d_in[2];
    const float* him  = (const float*)d_in[3];
    const float* W1   = (const float*)d_in[4];
    const float* b1   = (const float*)d_in[5];
    const float* W2   = (const float*)d_in[6];
    const float* b2   = (const float*)d_in[7];
    const float* bias = (const float*)d_in[8];
    float* out = (float*)d_out;

    dim3 rgrid(GX8, BB, 2);
    k_reduce<<<rgrid, RBT>>>(lre, lim, hre, him, W1, b1, W2, b2, bias);
    dim3 wgrid((NG + 255) / 256, BB);
    k_write<<<wgrid, 256>>>(out);
}